// round 3
// baseline (speedup 1.0000x reference)
#include <cuda_runtime.h>

#define MAXN 50000
#define MAXE 800000
#define HDIM 128
#define FE 64
#define FN 92
#define KX 192          // HDIM + FE
#define NLAYER 3
#define BN_EPS 1e-3f

// ---------------- scratch (static device globals; no allocation) ----------------
__device__ float d_h[MAXN * HDIM];        // node features
__device__ float d_X[MAXN * KX];          // [ sum h[col] | sum edge_attr ] per node
__device__ int   d_cnt[MAXN];             // in-degree counts (== deg before clip)
__device__ int   d_off[MAXN + 1];         // CSR offsets by destination (row)
__device__ int   d_cur[MAXN];             // scatter cursors
__device__ int   d_cols[MAXE];            // source node (col) sorted by destination
__device__ int   d_eid[MAXE];             // original edge id sorted by destination

// ---------------- CSR build ----------------
__global__ void k_zero_cnt(int n) {
    int i = blockIdx.x * blockDim.x + threadIdx.x;
    if (i < n) d_cnt[i] = 0;
}

__global__ void k_hist(const int* __restrict__ ei, int E) {
    int e = blockIdx.x * blockDim.x + threadIdx.x;
    if (e < E) atomicAdd(&d_cnt[ei[e]], 1);   // row = ei[e]
}

__global__ void k_scan(int N, int E) {
    __shared__ int s[1024];
    int t = threadIdx.x;
    int chunk = (N + 1023) >> 10;
    int lo = min(t * chunk, N);
    int hi = min(lo + chunk, N);
    int sum = 0;
    for (int i = lo; i < hi; i++) sum += d_cnt[i];
    s[t] = sum;
    __syncthreads();
    // inclusive Hillis-Steele scan over 1024 partials
    for (int d = 1; d < 1024; d <<= 1) {
        int v = (t >= d) ? s[t - d] : 0;
        __syncthreads();
        s[t] += v;
        __syncthreads();
    }
    int run = (t == 0) ? 0 : s[t - 1];
    for (int i = lo; i < hi; i++) {
        d_off[i] = run;
        d_cur[i] = run;
        run += d_cnt[i];
    }
    if (t == 0) d_off[N] = E;
}

__global__ void k_scatter(const int* __restrict__ ei, int E) {
    int e = blockIdx.x * blockDim.x + threadIdx.x;
    if (e < E) {
        int r = ei[e];
        int c = ei[E + e];
        int p = atomicAdd(&d_cur[r], 1);
        d_cols[p] = c;
        d_eid[p]  = e;
    }
}

// ---------------- S_e: per-destination sum of edge_attr into X[:,128:192] ----------------
__launch_bounds__(256)
__global__ void k_se(const float* __restrict__ ea, int N) {
    int gw   = (blockIdx.x * blockDim.x + threadIdx.x) >> 5;
    int lane = threadIdx.x & 31;
    if (gw >= N) return;
    int lo = d_off[gw], hi = d_off[gw + 1];
    float2 acc = make_float2(0.f, 0.f);
    int j = lo;
    for (; j + 2 <= hi; j += 2) {
        int e0 = d_eid[j], e1 = d_eid[j + 1];
        float2 v0 = *(const float2*)(ea + (size_t)e0 * FE + lane * 2);
        float2 v1 = *(const float2*)(ea + (size_t)e1 * FE + lane * 2);
        acc.x += v0.x + v1.x;
        acc.y += v0.y + v1.y;
    }
    if (j < hi) {
        int e0 = d_eid[j];
        float2 v0 = *(const float2*)(ea + (size_t)e0 * FE + lane * 2);
        acc.x += v0.x; acc.y += v0.y;
    }
    *(float2*)(d_X + (size_t)gw * KX + HDIM + lane * 2) = acc;
}

// ---------------- SpMM: X[:,0:128] = sum over in-edges of h[col] ----------------
__launch_bounds__(256)
__global__ void k_spmm(int N) {
    int gw   = (blockIdx.x * blockDim.x + threadIdx.x) >> 5;
    int lane = threadIdx.x & 31;
    if (gw >= N) return;
    int lo = d_off[gw], hi = d_off[gw + 1];
    float4 acc = make_float4(0.f, 0.f, 0.f, 0.f);
    int j = lo;
    for (; j + 4 <= hi; j += 4) {
        int c0 = d_cols[j],     c1 = d_cols[j + 1];
        int c2 = d_cols[j + 2], c3 = d_cols[j + 3];
        float4 v0 = *(const float4*)(d_h + (size_t)c0 * HDIM + lane * 4);
        float4 v1 = *(const float4*)(d_h + (size_t)c1 * HDIM + lane * 4);
        float4 v2 = *(const float4*)(d_h + (size_t)c2 * HDIM + lane * 4);
        float4 v3 = *(const float4*)(d_h + (size_t)c3 * HDIM + lane * 4);
        acc.x += (v0.x + v1.x) + (v2.x + v3.x);
        acc.y += (v0.y + v1.y) + (v2.y + v3.y);
        acc.z += (v0.z + v1.z) + (v2.z + v3.z);
        acc.w += (v0.w + v1.w) + (v2.w + v3.w);
    }
    for (; j < hi; j++) {
        int c0 = d_cols[j];
        float4 v0 = *(const float4*)(d_h + (size_t)c0 * HDIM + lane * 4);
        acc.x += v0.x; acc.y += v0.y; acc.z += v0.z; acc.w += v0.w;
    }
    *(float4*)(d_X + (size_t)gw * KX + lane * 4) = acc;
}

// ---------------- tiled fp32 GEMM: C[N,128] = A[N,K] @ W[K,128] + epilogue ----------------
// EPI==0 : emb      -> d_h = relu(A@W + bias)
// EPI==1 : layer    -> d_h += relu( ((X@W)/deg + bias) * gamma/sqrt(1+eps) + beta )
template <int K, int EPI>
__launch_bounds__(256)
__global__ void k_gemm(const float* __restrict__ Ain,
                       const float* __restrict__ W,
                       const float* __restrict__ bias,
                       const float* __restrict__ gamma,
                       const float* __restrict__ beta,
                       int N) {
    constexpr int KT = 16;
    constexpr int KTILES = (K + KT - 1) / KT;
    __shared__ __align__(16) float As[KT * 132];   // [k][row], padded stride
    __shared__ __align__(16) float Bs[KT * HDIM];  // [k][col]

    const float* A = (EPI == 1) ? (const float*)d_X : Ain;

    int tid = threadIdx.x;
    int tx = tid & 15;       // col group (8 cols)
    int ty = tid >> 4;       // row group (8 rows)
    int rowBase = blockIdx.x * 128;

    float acc[8][8];
#pragma unroll
    for (int i = 0; i < 8; i++)
#pragma unroll
        for (int j = 0; j < 8; j++) acc[i][j] = 0.f;

    for (int kt = 0; kt < KTILES; kt++) {
        int k0 = kt * KT;
        // A tile: 128 rows x 16 k, transposed store into As[k][row]
#pragma unroll
        for (int it = 0; it < 2; it++) {
            int i = tid + it * 256;      // 0..511
            int r = i >> 2;              // 0..127
            int q = i & 3;               // 0..3 (float4 within tile-k)
            int row = rowBase + r;
            int kg = k0 + q * 4;
            float4 v = make_float4(0.f, 0.f, 0.f, 0.f);
            if (row < N) {
                if (kg + 4 <= K) {
                    v = *(const float4*)(A + (size_t)row * K + kg);
                } else {
                    float tmp[4] = {0.f, 0.f, 0.f, 0.f};
#pragma unroll
                    for (int jj = 0; jj < 4; jj++)
                        if (kg + jj < K) tmp[jj] = A[(size_t)row * K + kg + jj];
                    v = make_float4(tmp[0], tmp[1], tmp[2], tmp[3]);
                }
            }
            As[(q * 4 + 0) * 132 + r] = v.x;
            As[(q * 4 + 1) * 132 + r] = v.y;
            As[(q * 4 + 2) * 132 + r] = v.z;
            As[(q * 4 + 3) * 132 + r] = v.w;
        }
        // B tile: 16 k x 128 cols
#pragma unroll
        for (int it = 0; it < 2; it++) {
            int i = tid + it * 256;      // 0..511
            int kk = i >> 5;             // 0..15
            int c4 = i & 31;             // 0..31
            int kg = k0 + kk;
            float4 v = make_float4(0.f, 0.f, 0.f, 0.f);
            if (kg < K) v = *(const float4*)(W + (size_t)kg * HDIM + c4 * 4);
            *(float4*)&Bs[kk * HDIM + c4 * 4] = v;
        }
        __syncthreads();
#pragma unroll
        for (int kk = 0; kk < KT; kk++) {
            float a[8], b[8];
            *(float4*)&a[0] = *(const float4*)&As[kk * 132 + ty * 8];
            *(float4*)&a[4] = *(const float4*)&As[kk * 132 + ty * 8 + 4];
            *(float4*)&b[0] = *(const float4*)&Bs[kk * HDIM + tx * 8];
            *(float4*)&b[4] = *(const float4*)&Bs[kk * HDIM + tx * 8 + 4];
#pragma unroll
            for (int i = 0; i < 8; i++)
#pragma unroll
                for (int j = 0; j < 8; j++)
                    acc[i][j] = fmaf(a[i], b[j], acc[i][j]);
        }
        __syncthreads();
    }

    int col0 = tx * 8;
#pragma unroll
    for (int i = 0; i < 8; i++) {
        int row = rowBase + ty * 8 + i;
        if (row >= N) continue;
        if (EPI == 0) {
#pragma unroll
            for (int j = 0; j < 8; j++) {
                float v = acc[i][j] + bias[col0 + j];
                d_h[(size_t)row * HDIM + col0 + j] = fmaxf(v, 0.f);
            }
        } else {
            float inv = 1.f / (float)max(d_cnt[row], 1);
            float sc = rsqrtf(1.f + BN_EPS);
#pragma unroll
            for (int j = 0; j < 8; j++) {
                int c = col0 + j;
                float v = acc[i][j] * inv + bias[c];
                v = v * (gamma[c] * sc) + beta[c];
                d_h[(size_t)row * HDIM + c] += fmaxf(v, 0.f);
            }
        }
    }
}

// ---------------- fused mean-pool + hidden + head (batch_idx sorted) ----------------
__launch_bounds__(128)
__global__ void k_head(const int* __restrict__ batch,
                       const float* __restrict__ Wh,
                       const float* __restrict__ bh,
                       const float* __restrict__ Wout,
                       const float* __restrict__ bout,
                       float* __restrict__ out, int N) {
    int b = blockIdx.x;
    int t = threadIdx.x;
    __shared__ float gv[HDIM];
    __shared__ float red[HDIM];
    __shared__ int srange[2];
    if (t < 2) {
        int v = b + t;
        int lo = 0, hi = N;
        while (lo < hi) {
            int m = (lo + hi) >> 1;
            if (batch[m] < v) lo = m + 1; else hi = m;
        }
        srange[t] = lo;
    }
    __syncthreads();
    int lo = srange[0], hi = srange[1];
    float s = 0.f;
    for (int r = lo; r < hi; r++) s += d_h[(size_t)r * HDIM + t];
    gv[t] = s / (float)max(hi - lo, 1);
    __syncthreads();
    float hd = bh[t];
#pragma unroll 8
    for (int k = 0; k < HDIM; k++) hd = fmaf(gv[k], Wh[k * HDIM + t], hd);
    hd = fmaxf(hd, 0.f);
    red[t] = hd * Wout[t];
    __syncthreads();
    for (int s2 = 64; s2 > 0; s2 >>= 1) {
        if (t < s2) red[t] += red[t + s2];
        __syncthreads();
    }
    if (t == 0) out[b] = red[0] + bout[0];
}

// ---------------- launch ----------------
extern "C" void kernel_launch(void* const* d_in, const int* in_sizes, int n_in,
                              void* d_out, int out_size) {
    const float* x     = (const float*)d_in[0];
    const int*   ei    = (const int*)  d_in[1];
    const float* ea    = (const float*)d_in[2];
    const int*   batch = (const int*)  d_in[3];
    const float* W_emb = (const float*)d_in[4];
    const float* b_emb = (const float*)d_in[5];
    const float* Wc    = (const float*)d_in[6];
    const float* bc    = (const float*)d_in[7];
    const float* gamma = (const float*)d_in[8];
    const float* beta  = (const float*)d_in[9];
    const float* Wh    = (const float*)d_in[10];
    const float* bh    = (const float*)d_in[11];
    const float* Wout  = (const float*)d_in[12];
    const float* bout  = (const float*)d_in[13];
    float* out = (float*)d_out;

    int N = in_sizes[0] / FN;
    int E = in_sizes[1] / 2;
    int G = out_size;

    // CSR by destination node
    k_zero_cnt<<<(N + 255) / 256, 256>>>(N);
    k_hist<<<(E + 255) / 256, 256>>>(ei, E);
    k_scan<<<1, 1024>>>(N, E);
    k_scatter<<<(E + 255) / 256, 256>>>(ei, E);

    // embedding: h = relu(x @ W_emb + b_emb)
    k_gemm<FN, 0><<<(N + 127) / 128, 256>>>(x, W_emb, b_emb, nullptr, nullptr, N);

    // layer-invariant edge-attr aggregation into X[:,128:192]
    k_se<<<(N * 32 + 255) / 256, 256>>>(ea, N);

    for (int l = 0; l < NLAYER; l++) {
        k_spmm<<<(N * 32 + 255) / 256, 256>>>(N);
        k_gemm<KX, 1><<<(N + 127) / 128, 256>>>(nullptr, Wc + (size_t)l * KX * HDIM,
                                                bc + l * HDIM, gamma + l * HDIM,
                                                beta + l * HDIM, N);
    }

    k_head<<<G, 128>>>(batch, Wh, bh, Wout, bout, out, N);
}

// round 4
// speedup vs baseline: 1.4085x; 1.4085x over previous
#include <cuda_runtime.h>
#include <cstdint>

#define MAXN 50000
#define MAXE 800000
#define HDIM 128
#define FE 64
#define FN 92
#define KX 192          // HDIM + FE
#define NLAYER 3
#define BN_EPS 1e-3f

// ---------------- scratch (static device globals; no allocation) ----------------
__device__ float d_h[MAXN * HDIM];        // node features
__device__ float d_X[MAXN * KX];          // [ sum h[col] | sum edge_attr ] per node
__device__ int   d_cnt[MAXN];             // in-degree counts
__device__ int   d_off[MAXN + 1];         // CSR offsets by destination (row)
__device__ int   d_cur[MAXN];             // scatter cursors
__device__ int   d_cols[MAXE];            // source node (col) sorted by destination
__device__ int   d_eid[MAXE];             // original edge id sorted by destination

// ---------------- CSR build ----------------
__global__ void k_zero_cnt(int n) {
    int i = blockIdx.x * blockDim.x + threadIdx.x;
    if (i < n) d_cnt[i] = 0;
}

__global__ void k_hist(const int* __restrict__ ei, int E) {
    int e = blockIdx.x * blockDim.x + threadIdx.x;
    if (e < E) atomicAdd(&d_cnt[ei[e]], 1);
}

__global__ void k_scan(int N, int E) {
    __shared__ int s[1024];
    int t = threadIdx.x;
    int chunk = (N + 1023) >> 10;
    int lo = min(t * chunk, N);
    int hi = min(lo + chunk, N);
    int sum = 0;
    for (int i = lo; i < hi; i++) sum += d_cnt[i];
    s[t] = sum;
    __syncthreads();
    for (int d = 1; d < 1024; d <<= 1) {
        int v = (t >= d) ? s[t - d] : 0;
        __syncthreads();
        s[t] += v;
        __syncthreads();
    }
    int run = (t == 0) ? 0 : s[t - 1];
    for (int i = lo; i < hi; i++) {
        d_off[i] = run;
        d_cur[i] = run;
        run += d_cnt[i];
    }
    if (t == 0) d_off[N] = E;
}

__global__ void k_scatter(const int* __restrict__ ei, int E) {
    int e = blockIdx.x * blockDim.x + threadIdx.x;
    if (e < E) {
        int r = ei[e];
        int c = ei[E + e];
        int p = atomicAdd(&d_cur[r], 1);
        d_cols[p] = c;
        d_eid[p]  = e;
    }
}

// ---------------- S_e: per-destination sum of edge_attr into X[:,128:192] ----------------
__launch_bounds__(256)
__global__ void k_se(const float* __restrict__ ea, int N) {
    int gw   = (blockIdx.x * blockDim.x + threadIdx.x) >> 5;
    int lane = threadIdx.x & 31;
    if (gw >= N) return;
    int lo = d_off[gw], hi = d_off[gw + 1];
    float2 acc = make_float2(0.f, 0.f);
    int j = lo;
    for (; j + 4 <= hi; j += 4) {
        int e0 = d_eid[j],     e1 = d_eid[j + 1];
        int e2 = d_eid[j + 2], e3 = d_eid[j + 3];
        float2 v0 = *(const float2*)(ea + (size_t)e0 * FE + lane * 2);
        float2 v1 = *(const float2*)(ea + (size_t)e1 * FE + lane * 2);
        float2 v2 = *(const float2*)(ea + (size_t)e2 * FE + lane * 2);
        float2 v3 = *(const float2*)(ea + (size_t)e3 * FE + lane * 2);
        acc.x += (v0.x + v1.x) + (v2.x + v3.x);
        acc.y += (v0.y + v1.y) + (v2.y + v3.y);
    }
    for (; j < hi; j++) {
        int e0 = d_eid[j];
        float2 v0 = *(const float2*)(ea + (size_t)e0 * FE + lane * 2);
        acc.x += v0.x; acc.y += v0.y;
    }
    *(float2*)(d_X + (size_t)gw * KX + HDIM + lane * 2) = acc;
}

// ---------------- SpMM: X[:,0:128] = sum over in-edges of h[col] ----------------
__launch_bounds__(256)
__global__ void k_spmm(int N) {
    int gw   = (blockIdx.x * blockDim.x + threadIdx.x) >> 5;
    int lane = threadIdx.x & 31;
    if (gw >= N) return;
    int lo = d_off[gw], hi = d_off[gw + 1];
    float4 acc = make_float4(0.f, 0.f, 0.f, 0.f);
    int j = lo;
    for (; j + 4 <= hi; j += 4) {
        int c0 = d_cols[j],     c1 = d_cols[j + 1];
        int c2 = d_cols[j + 2], c3 = d_cols[j + 3];
        float4 v0 = *(const float4*)(d_h + (size_t)c0 * HDIM + lane * 4);
        float4 v1 = *(const float4*)(d_h + (size_t)c1 * HDIM + lane * 4);
        float4 v2 = *(const float4*)(d_h + (size_t)c2 * HDIM + lane * 4);
        float4 v3 = *(const float4*)(d_h + (size_t)c3 * HDIM + lane * 4);
        acc.x += (v0.x + v1.x) + (v2.x + v3.x);
        acc.y += (v0.y + v1.y) + (v2.y + v3.y);
        acc.z += (v0.z + v1.z) + (v2.z + v3.z);
        acc.w += (v0.w + v1.w) + (v2.w + v3.w);
    }
    for (; j < hi; j++) {
        int c0 = d_cols[j];
        float4 v0 = *(const float4*)(d_h + (size_t)c0 * HDIM + lane * 4);
        acc.x += v0.x; acc.y += v0.y; acc.z += v0.z; acc.w += v0.w;
    }
    *(float4*)(d_X + (size_t)gw * KX + lane * 4) = acc;
}

// ---------------- tf32 tensor-core GEMM: C[N,128] = A[N,K] @ W[K,128] + epilogue ----------------
// EPI==0 : emb   -> d_h = relu(A@W + bias)
// EPI==1 : layer -> d_h += relu( ((X@W)/deg + bias) * gamma/sqrt(1+eps) + beta )
__device__ __forceinline__ uint32_t f2tf32(float f) {
    uint32_t r;
    asm("cvt.rna.tf32.f32 %0, %1;" : "=r"(r) : "f"(f));
    return r;
}

template <int K, int EPI>
__launch_bounds__(256)
__global__ void k_gemm_tc(const float* __restrict__ Ain,
                          const float* __restrict__ W,
                          const float* __restrict__ bias,
                          const float* __restrict__ gamma,
                          const float* __restrict__ beta,
                          int N) {
    constexpr int KC = 32;
    constexpr int KTILES = (K + KC - 1) / KC;
    constexpr int AS_STRIDE = 36;   // 128 x 32, padded
    constexpr int BS_STRIDE = 132;  // 32 x 128, padded
    __shared__ __align__(16) float As[128 * AS_STRIDE];
    __shared__ __align__(16) float Bs[32 * BS_STRIDE];

    const float* A = (EPI == 1) ? (const float*)d_X : Ain;

    const int tid  = threadIdx.x;
    const int wid  = tid >> 5;
    const int lane = tid & 31;
    const int warp_m = wid & 3;   // 0..3 -> 32-row slabs
    const int warp_n = wid >> 2;  // 0..1 -> 64-col slabs
    const int gID = lane >> 2;    // group id 0..7
    const int tig = lane & 3;     // thread-in-group 0..3
    const int rowBase = blockIdx.x * 128;

    float acc[2][8][4];
#pragma unroll
    for (int mf = 0; mf < 2; mf++)
#pragma unroll
        for (int nf = 0; nf < 8; nf++)
#pragma unroll
            for (int c = 0; c < 4; c++) acc[mf][nf][c] = 0.f;

    for (int kt = 0; kt < KTILES; kt++) {
        const int k0 = kt * KC;
        // stage A: 128 rows x 32 k (1024 float4, 4 per thread)
        {
            int r = tid >> 3;          // 0..31
            int k4 = (tid & 7) * 4;    // 0,4,..,28
#pragma unroll
            for (int it = 0; it < 4; it++) {
                int row = r + it * 32;
                int grow = rowBase + row;
                int kg = k0 + k4;
                float4 v = make_float4(0.f, 0.f, 0.f, 0.f);
                if (grow < N && kg + 4 <= K)
                    v = *(const float4*)(A + (size_t)grow * K + kg);
                *(float4*)&As[row * AS_STRIDE + k4] = v;
            }
        }
        // stage B: 32 k x 128 n (1024 float4, 4 per thread)
        {
            int kk = tid >> 5;         // 0..7
            int c4 = (tid & 31) * 4;   // 0..124
#pragma unroll
            for (int it = 0; it < 4; it++) {
                int krow = kk + it * 8;
                int kg = k0 + krow;
                float4 v = make_float4(0.f, 0.f, 0.f, 0.f);
                if (kg < K)
                    v = *(const float4*)(W + (size_t)kg * HDIM + c4);
                *(float4*)&Bs[krow * BS_STRIDE + c4] = v;
            }
        }
        __syncthreads();

#pragma unroll
        for (int k8 = 0; k8 < KC / 8; k8++) {
            const int kb = k8 * 8;
            // B fragments: 8 n-frags x 2 regs
            uint32_t bfr[8][2];
#pragma unroll
            for (int nf = 0; nf < 8; nf++) {
                int col = warp_n * 64 + nf * 8 + gID;
                bfr[nf][0] = f2tf32(Bs[(kb + tig) * BS_STRIDE + col]);
                bfr[nf][1] = f2tf32(Bs[(kb + tig + 4) * BS_STRIDE + col]);
            }
#pragma unroll
            for (int mf = 0; mf < 2; mf++) {
                int r0 = warp_m * 32 + mf * 16 + gID;
                uint32_t a0 = f2tf32(As[r0 * AS_STRIDE + kb + tig]);
                uint32_t a1 = f2tf32(As[(r0 + 8) * AS_STRIDE + kb + tig]);
                uint32_t a2 = f2tf32(As[r0 * AS_STRIDE + kb + tig + 4]);
                uint32_t a3 = f2tf32(As[(r0 + 8) * AS_STRIDE + kb + tig + 4]);
#pragma unroll
                for (int nf = 0; nf < 8; nf++) {
                    asm volatile(
                        "mma.sync.aligned.m16n8k8.row.col.f32.tf32.tf32.f32 "
                        "{%0,%1,%2,%3}, {%4,%5,%6,%7}, {%8,%9}, {%0,%1,%2,%3};\n"
                        : "+f"(acc[mf][nf][0]), "+f"(acc[mf][nf][1]),
                          "+f"(acc[mf][nf][2]), "+f"(acc[mf][nf][3])
                        : "r"(a0), "r"(a1), "r"(a2), "r"(a3),
                          "r"(bfr[nf][0]), "r"(bfr[nf][1]));
                }
            }
        }
        __syncthreads();
    }

    // epilogue
    const float sc = rsqrtf(1.f + BN_EPS);
#pragma unroll
    for (int mf = 0; mf < 2; mf++) {
        int r0 = rowBase + warp_m * 32 + mf * 16 + gID;
        int r1 = r0 + 8;
        float inv0 = 1.f, inv1 = 1.f;
        if (EPI == 1) {
            if (r0 < N) inv0 = 1.f / (float)max(d_cnt[r0], 1);
            if (r1 < N) inv1 = 1.f / (float)max(d_cnt[r1], 1);
        }
#pragma unroll
        for (int nf = 0; nf < 8; nf++) {
            int c0 = warp_n * 64 + nf * 8 + 2 * tig;
#pragma unroll
            for (int cc = 0; cc < 2; cc++) {
                int c = c0 + cc;
                float b  = bias[c];
                if (EPI == 0) {
                    if (r0 < N) d_h[(size_t)r0 * HDIM + c] = fmaxf(acc[mf][nf][cc] + b, 0.f);
                    if (r1 < N) d_h[(size_t)r1 * HDIM + c] = fmaxf(acc[mf][nf][2 + cc] + b, 0.f);
                } else {
                    float g = gamma[c] * sc;
                    float be = beta[c];
                    if (r0 < N) {
                        float v = acc[mf][nf][cc] * inv0 + b;
                        v = v * g + be;
                        d_h[(size_t)r0 * HDIM + c] += fmaxf(v, 0.f);
                    }
                    if (r1 < N) {
                        float v = acc[mf][nf][2 + cc] * inv1 + b;
                        v = v * g + be;
                        d_h[(size_t)r1 * HDIM + c] += fmaxf(v, 0.f);
                    }
                }
            }
        }
    }
}

// ---------------- fused mean-pool + hidden + head (batch_idx sorted) ----------------
__launch_bounds__(128)
__global__ void k_head(const int* __restrict__ batch,
                       const float* __restrict__ Wh,
                       const float* __restrict__ bh,
                       const float* __restrict__ Wout,
                       const float* __restrict__ bout,
                       float* __restrict__ out, int N) {
    int b = blockIdx.x;
    int t = threadIdx.x;
    __shared__ float gv[HDIM];
    __shared__ float red[HDIM];
    __shared__ int srange[2];
    if (t < 2) {
        int v = b + t;
        int lo = 0, hi = N;
        while (lo < hi) {
            int m = (lo + hi) >> 1;
            if (batch[m] < v) lo = m + 1; else hi = m;
        }
        srange[t] = lo;
    }
    __syncthreads();
    int lo = srange[0], hi = srange[1];
    float s = 0.f;
    for (int r = lo; r < hi; r++) s += d_h[(size_t)r * HDIM + t];
    gv[t] = s / (float)max(hi - lo, 1);
    __syncthreads();
    float hd = bh[t];
#pragma unroll 8
    for (int k = 0; k < HDIM; k++) hd = fmaf(gv[k], Wh[k * HDIM + t], hd);
    hd = fmaxf(hd, 0.f);
    red[t] = hd * Wout[t];
    __syncthreads();
    for (int s2 = 64; s2 > 0; s2 >>= 1) {
        if (t < s2) red[t] += red[t + s2];
        __syncthreads();
    }
    if (t == 0) out[b] = red[0] + bout[0];
}

// ---------------- launch ----------------
extern "C" void kernel_launch(void* const* d_in, const int* in_sizes, int n_in,
                              void* d_out, int out_size) {
    const float* x     = (const float*)d_in[0];
    const int*   ei    = (const int*)  d_in[1];
    const float* ea    = (const float*)d_in[2];
    const int*   batch = (const int*)  d_in[3];
    const float* W_emb = (const float*)d_in[4];
    const float* b_emb = (const float*)d_in[5];
    const float* Wc    = (const float*)d_in[6];
    const float* bc    = (const float*)d_in[7];
    const float* gamma = (const float*)d_in[8];
    const float* beta  = (const float*)d_in[9];
    const float* Wh    = (const float*)d_in[10];
    const float* bh    = (const float*)d_in[11];
    const float* Wout  = (const float*)d_in[12];
    const float* bout  = (const float*)d_in[13];
    float* out = (float*)d_out;

    int N = in_sizes[0] / FN;
    int E = in_sizes[1] / 2;
    int G = out_size;

    // CSR by destination node
    k_zero_cnt<<<(N + 255) / 256, 256>>>(N);
    k_hist<<<(E + 255) / 256, 256>>>(ei, E);
    k_scan<<<1, 1024>>>(N, E);
    k_scatter<<<(E + 255) / 256, 256>>>(ei, E);

    // embedding: h = relu(x @ W_emb + b_emb)
    k_gemm_tc<FN, 0><<<(N + 127) / 128, 256>>>(x, W_emb, b_emb, nullptr, nullptr, N);

    // layer-invariant edge-attr aggregation into X[:,128:192]
    k_se<<<(N * 32 + 255) / 256, 256>>>(ea, N);

    for (int l = 0; l < NLAYER; l++) {
        k_spmm<<<(N * 32 + 255) / 256, 256>>>(N);
        k_gemm_tc<KX, 1><<<(N + 127) / 128, 256>>>(nullptr, Wc + (size_t)l * KX * HDIM,
                                                   bc + l * HDIM, gamma + l * HDIM,
                                                   beta + l * HDIM, N);
    }

    k_head<<<G, 128>>>(batch, Wh, bh, Wout, bout, out, N);
}

// round 5
// speedup vs baseline: 1.5358x; 1.0904x over previous
#include <cuda_runtime.h>
#include <cuda_fp16.h>
#include <cstdint>

#define MAXN 50000
#define MAXE 800000
#define HDIM 128
#define FE 64
#define FN 92
#define KX 192          // HDIM + FE
#define NLAYER 3
#define BN_EPS 1e-3f

// ---------------- scratch (static device globals; no allocation) ----------------
__device__ float  d_h[MAXN * HDIM];        // node features (fp32, for residual+pool)
__device__ __half d_hh[MAXN * HDIM];       // fp16 mirror of h (SpMM gather source)
__device__ float  d_X[MAXN * KX];          // [ sum h[col] | sum edge_attr ] per node
__device__ int    d_cnt[MAXN];             // in-degree counts
__device__ int    d_off[MAXN + 1];         // CSR offsets by destination (row)
__device__ int    d_cur[MAXN];             // scatter cursors
__device__ int    d_cols[MAXE];            // source node (col) sorted by destination
__device__ int    d_eid[MAXE];             // original edge id sorted by destination
__device__ int    d_bsum[64];              // per-block scan totals
__device__ int    d_bbase[64];             // per-block scan bases

struct __align__(8) H4 { __half2 a, b; };

// ---------------- CSR build ----------------
__global__ void k_zero_cnt(int n) {
    int i = blockIdx.x * blockDim.x + threadIdx.x;
    if (i < n) d_cnt[i] = 0;
}

__global__ void k_hist(const int* __restrict__ ei, int E) {
    int e = blockIdx.x * blockDim.x + threadIdx.x;
    if (e < E) atomicAdd(&d_cnt[ei[e]], 1);
}

// block-local exclusive scan of d_cnt into d_off (temp), block totals to d_bsum
__global__ void k_scan1(int N) {
    __shared__ int s[32];
    int t = threadIdx.x;
    int i = blockIdx.x * 1024 + t;
    int lane = t & 31, w = t >> 5;
    int c = (i < N) ? d_cnt[i] : 0;
    int v = c;
#pragma unroll
    for (int d = 1; d < 32; d <<= 1) {
        int u = __shfl_up_sync(0xffffffffu, v, d);
        if (lane >= d) v += u;
    }
    if (lane == 31) s[w] = v;
    __syncthreads();
    if (w == 0) {
        int sv = s[lane];
#pragma unroll
        for (int d = 1; d < 32; d <<= 1) {
            int u = __shfl_up_sync(0xffffffffu, sv, d);
            if (lane >= d) sv += u;
        }
        s[lane] = sv;
    }
    __syncthreads();
    int base = (w > 0) ? s[w - 1] : 0;
    int incl = v + base;
    if (i < N) d_off[i] = incl - c;        // block-local exclusive
    if (t == 1023) d_bsum[blockIdx.x] = incl;
}

// exclusive scan of block totals (NB <= 64), 1 block of 64 threads
__global__ void k_scan2(int NB) {
    __shared__ int s[2];
    int t = threadIdx.x;
    int lane = t & 31, w = t >> 5;
    int c = (t < NB) ? d_bsum[t] : 0;
    int v = c;
#pragma unroll
    for (int d = 1; d < 32; d <<= 1) {
        int u = __shfl_up_sync(0xffffffffu, v, d);
        if (lane >= d) v += u;
    }
    if (lane == 31) s[w] = v;
    __syncthreads();
    int base = (w > 0) ? s[0] : 0;
    if (t < NB) d_bbase[t] = v + base - c;  // exclusive
}

__global__ void k_scan3(int N, int E) {
    int i = blockIdx.x * blockDim.x + threadIdx.x;
    if (i < N) {
        int v = d_off[i] + d_bbase[i >> 10];
        d_off[i] = v;
        d_cur[i] = v;
    }
    if (i == 0) d_off[N] = E;
}

__global__ void k_scatter(const int* __restrict__ ei, int E) {
    int e = blockIdx.x * blockDim.x + threadIdx.x;
    if (e < E) {
        int r = ei[e];
        int c = ei[E + e];
        int p = atomicAdd(&d_cur[r], 1);
        d_cols[p] = c;
        d_eid[p]  = e;
    }
}

// ---------------- S_e: per-destination sum of edge_attr into X[:,128:192] ----------------
__launch_bounds__(256)
__global__ void k_se(const float* __restrict__ ea, int N) {
    int gw   = (blockIdx.x * blockDim.x + threadIdx.x) >> 5;
    int lane = threadIdx.x & 31;
    if (gw >= N) return;
    int lo = d_off[gw], hi = d_off[gw + 1];
    float2 acc = make_float2(0.f, 0.f);
    int j = lo;
    for (; j + 4 <= hi; j += 4) {
        int e0 = d_eid[j],     e1 = d_eid[j + 1];
        int e2 = d_eid[j + 2], e3 = d_eid[j + 3];
        float2 v0 = *(const float2*)(ea + (size_t)e0 * FE + lane * 2);
        float2 v1 = *(const float2*)(ea + (size_t)e1 * FE + lane * 2);
        float2 v2 = *(const float2*)(ea + (size_t)e2 * FE + lane * 2);
        float2 v3 = *(const float2*)(ea + (size_t)e3 * FE + lane * 2);
        acc.x += (v0.x + v1.x) + (v2.x + v3.x);
        acc.y += (v0.y + v1.y) + (v2.y + v3.y);
    }
    for (; j < hi; j++) {
        int e0 = d_eid[j];
        float2 v0 = *(const float2*)(ea + (size_t)e0 * FE + lane * 2);
        acc.x += v0.x; acc.y += v0.y;
    }
    *(float2*)(d_X + (size_t)gw * KX + HDIM + lane * 2) = acc;
}

// ---------------- SpMM (fp16 gather): X[:,0:128] = sum over in-edges of h[col] ----------------
__launch_bounds__(256)
__global__ void k_spmm(int N) {
    int gw   = (blockIdx.x * blockDim.x + threadIdx.x) >> 5;
    int lane = threadIdx.x & 31;
    if (gw >= N) return;
    int lo = d_off[gw], hi = d_off[gw + 1];
    float4 acc = make_float4(0.f, 0.f, 0.f, 0.f);
    int j = lo;
    for (; j + 4 <= hi; j += 4) {
        int c0 = d_cols[j],     c1 = d_cols[j + 1];
        int c2 = d_cols[j + 2], c3 = d_cols[j + 3];
        H4 v0 = *(const H4*)(d_hh + (size_t)c0 * HDIM + lane * 4);
        H4 v1 = *(const H4*)(d_hh + (size_t)c1 * HDIM + lane * 4);
        H4 v2 = *(const H4*)(d_hh + (size_t)c2 * HDIM + lane * 4);
        H4 v3 = *(const H4*)(d_hh + (size_t)c3 * HDIM + lane * 4);
        float2 a0 = __half22float2(v0.a), b0 = __half22float2(v0.b);
        float2 a1 = __half22float2(v1.a), b1 = __half22float2(v1.b);
        float2 a2 = __half22float2(v2.a), b2 = __half22float2(v2.b);
        float2 a3 = __half22float2(v3.a), b3 = __half22float2(v3.b);
        acc.x += (a0.x + a1.x) + (a2.x + a3.x);
        acc.y += (a0.y + a1.y) + (a2.y + a3.y);
        acc.z += (b0.x + b1.x) + (b2.x + b3.x);
        acc.w += (b0.y + b1.y) + (b2.y + b3.y);
    }
    for (; j < hi; j++) {
        int c0 = d_cols[j];
        H4 v0 = *(const H4*)(d_hh + (size_t)c0 * HDIM + lane * 4);
        float2 a0 = __half22float2(v0.a), b0 = __half22float2(v0.b);
        acc.x += a0.x; acc.y += a0.y; acc.z += b0.x; acc.w += b0.y;
    }
    *(float4*)(d_X + (size_t)gw * KX + lane * 4) = acc;
}

// ---------------- tf32 tensor-core GEMM: C[N,128] = A[N,K] @ W[K,128] + epilogue ----------------
__device__ __forceinline__ uint32_t f2tf32(float f) {
    uint32_t r;
    asm("cvt.rna.tf32.f32 %0, %1;" : "=r"(r) : "f"(f));
    return r;
}

template <int K, int EPI>
__launch_bounds__(256)
__global__ void k_gemm_tc(const float* __restrict__ Ain,
                          const float* __restrict__ W,
                          const float* __restrict__ bias,
                          const float* __restrict__ gamma,
                          const float* __restrict__ beta,
                          int N) {
    constexpr int KC = 32;
    constexpr int KTILES = (K + KC - 1) / KC;
    constexpr int AS_STRIDE = 36;   // 128 x 32, padded
    constexpr int BS_STRIDE = 132;  // 32 x 128, padded
    __shared__ __align__(16) float As[128 * AS_STRIDE];
    __shared__ __align__(16) float Bs[32 * BS_STRIDE];

    const float* A = (EPI == 1) ? (const float*)d_X : Ain;

    const int tid  = threadIdx.x;
    const int wid  = tid >> 5;
    const int lane = tid & 31;
    const int warp_m = wid & 3;   // 0..3 -> 32-row slabs
    const int warp_n = wid >> 2;  // 0..1 -> 64-col slabs
    const int gID = lane >> 2;    // group id 0..7
    const int tig = lane & 3;     // thread-in-group 0..3
    const int rowBase = blockIdx.x * 128;

    float acc[2][8][4];
#pragma unroll
    for (int mf = 0; mf < 2; mf++)
#pragma unroll
        for (int nf = 0; nf < 8; nf++)
#pragma unroll
            for (int c = 0; c < 4; c++) acc[mf][nf][c] = 0.f;

    for (int kt = 0; kt < KTILES; kt++) {
        const int k0 = kt * KC;
        // stage A: 128 rows x 32 k
        {
            int r = tid >> 3;          // 0..31
            int k4 = (tid & 7) * 4;    // 0,4,..,28
#pragma unroll
            for (int it = 0; it < 4; it++) {
                int row = r + it * 32;
                int grow = rowBase + row;
                int kg = k0 + k4;
                float4 v = make_float4(0.f, 0.f, 0.f, 0.f);
                if (grow < N && kg + 4 <= K)
                    v = *(const float4*)(A + (size_t)grow * K + kg);
                *(float4*)&As[row * AS_STRIDE + k4] = v;
            }
        }
        // stage B: 32 k x 128 n
        {
            int kk = tid >> 5;         // 0..7
            int c4 = (tid & 31) * 4;   // 0..124
#pragma unroll
            for (int it = 0; it < 4; it++) {
                int krow = kk + it * 8;
                int kg = k0 + krow;
                float4 v = make_float4(0.f, 0.f, 0.f, 0.f);
                if (kg < K)
                    v = *(const float4*)(W + (size_t)kg * HDIM + c4);
                *(float4*)&Bs[krow * BS_STRIDE + c4] = v;
            }
        }
        __syncthreads();

#pragma unroll
        for (int k8 = 0; k8 < KC / 8; k8++) {
            const int kb = k8 * 8;
            uint32_t bfr[8][2];
#pragma unroll
            for (int nf = 0; nf < 8; nf++) {
                int col = warp_n * 64 + nf * 8 + gID;
                bfr[nf][0] = f2tf32(Bs[(kb + tig) * BS_STRIDE + col]);
                bfr[nf][1] = f2tf32(Bs[(kb + tig + 4) * BS_STRIDE + col]);
            }
#pragma unroll
            for (int mf = 0; mf < 2; mf++) {
                int r0 = warp_m * 32 + mf * 16 + gID;
                uint32_t a0 = f2tf32(As[r0 * AS_STRIDE + kb + tig]);
                uint32_t a1 = f2tf32(As[(r0 + 8) * AS_STRIDE + kb + tig]);
                uint32_t a2 = f2tf32(As[r0 * AS_STRIDE + kb + tig + 4]);
                uint32_t a3 = f2tf32(As[(r0 + 8) * AS_STRIDE + kb + tig + 4]);
#pragma unroll
                for (int nf = 0; nf < 8; nf++) {
                    asm volatile(
                        "mma.sync.aligned.m16n8k8.row.col.f32.tf32.tf32.f32 "
                        "{%0,%1,%2,%3}, {%4,%5,%6,%7}, {%8,%9}, {%0,%1,%2,%3};\n"
                        : "+f"(acc[mf][nf][0]), "+f"(acc[mf][nf][1]),
                          "+f"(acc[mf][nf][2]), "+f"(acc[mf][nf][3])
                        : "r"(a0), "r"(a1), "r"(a2), "r"(a3),
                          "r"(bfr[nf][0]), "r"(bfr[nf][1]));
                }
            }
        }
        __syncthreads();
    }

    // epilogue: write fp32 d_h and fp16 mirror d_hh
    const float sc = rsqrtf(1.f + BN_EPS);
#pragma unroll
    for (int mf = 0; mf < 2; mf++) {
        int r0 = rowBase + warp_m * 32 + mf * 16 + gID;
        int r1 = r0 + 8;
        float inv0 = 1.f, inv1 = 1.f;
        if (EPI == 1) {
            if (r0 < N) inv0 = 1.f / (float)max(d_cnt[r0], 1);
            if (r1 < N) inv1 = 1.f / (float)max(d_cnt[r1], 1);
        }
#pragma unroll
        for (int nf = 0; nf < 8; nf++) {
            int c0 = warp_n * 64 + nf * 8 + 2 * tig;
#pragma unroll
            for (int cc = 0; cc < 2; cc++) {
                int c = c0 + cc;
                float b = bias[c];
                if (EPI == 0) {
                    if (r0 < N) {
                        float v = fmaxf(acc[mf][nf][cc] + b, 0.f);
                        d_h[(size_t)r0 * HDIM + c] = v;
                        d_hh[(size_t)r0 * HDIM + c] = __float2half_rn(v);
                    }
                    if (r1 < N) {
                        float v = fmaxf(acc[mf][nf][2 + cc] + b, 0.f);
                        d_h[(size_t)r1 * HDIM + c] = v;
                        d_hh[(size_t)r1 * HDIM + c] = __float2half_rn(v);
                    }
                } else {
                    float g = gamma[c] * sc;
                    float be = beta[c];
                    if (r0 < N) {
                        float v = acc[mf][nf][cc] * inv0 + b;
                        v = v * g + be;
                        float nh = d_h[(size_t)r0 * HDIM + c] + fmaxf(v, 0.f);
                        d_h[(size_t)r0 * HDIM + c] = nh;
                        d_hh[(size_t)r0 * HDIM + c] = __float2half_rn(nh);
                    }
                    if (r1 < N) {
                        float v = acc[mf][nf][2 + cc] * inv1 + b;
                        v = v * g + be;
                        float nh = d_h[(size_t)r1 * HDIM + c] + fmaxf(v, 0.f);
                        d_h[(size_t)r1 * HDIM + c] = nh;
                        d_hh[(size_t)r1 * HDIM + c] = __float2half_rn(nh);
                    }
                }
            }
        }
    }
}

// ---------------- fused mean-pool + hidden + head (batch_idx sorted) ----------------
__launch_bounds__(128)
__global__ void k_head(const int* __restrict__ batch,
                       const float* __restrict__ Wh,
                       const float* __restrict__ bh,
                       const float* __restrict__ Wout,
                       const float* __restrict__ bout,
                       float* __restrict__ out, int N) {
    int b = blockIdx.x;
    int t = threadIdx.x;
    __shared__ float gv[HDIM];
    __shared__ float red[HDIM];
    __shared__ int srange[2];
    if (t < 2) {
        int v = b + t;
        int lo = 0, hi = N;
        while (lo < hi) {
            int m = (lo + hi) >> 1;
            if (batch[m] < v) lo = m + 1; else hi = m;
        }
        srange[t] = lo;
    }
    __syncthreads();
    int lo = srange[0], hi = srange[1];
    float s = 0.f;
    for (int r = lo; r < hi; r++) s += d_h[(size_t)r * HDIM + t];
    gv[t] = s / (float)max(hi - lo, 1);
    __syncthreads();
    float hd = bh[t];
#pragma unroll 8
    for (int k = 0; k < HDIM; k++) hd = fmaf(gv[k], Wh[k * HDIM + t], hd);
    hd = fmaxf(hd, 0.f);
    red[t] = hd * Wout[t];
    __syncthreads();
    for (int s2 = 64; s2 > 0; s2 >>= 1) {
        if (t < s2) red[t] += red[t + s2];
        __syncthreads();
    }
    if (t == 0) out[b] = red[0] + bout[0];
}

// ---------------- launch ----------------
extern "C" void kernel_launch(void* const* d_in, const int* in_sizes, int n_in,
                              void* d_out, int out_size) {
    const float* x     = (const float*)d_in[0];
    const int*   ei    = (const int*)  d_in[1];
    const float* ea    = (const float*)d_in[2];
    const int*   batch = (const int*)  d_in[3];
    const float* W_emb = (const float*)d_in[4];
    const float* b_emb = (const float*)d_in[5];
    const float* Wc    = (const float*)d_in[6];
    const float* bc    = (const float*)d_in[7];
    const float* gamma = (const float*)d_in[8];
    const float* beta  = (const float*)d_in[9];
    const float* Wh    = (const float*)d_in[10];
    const float* bh    = (const float*)d_in[11];
    const float* Wout  = (const float*)d_in[12];
    const float* bout  = (const float*)d_in[13];
    float* out = (float*)d_out;

    int N = in_sizes[0] / FN;
    int E = in_sizes[1] / 2;
    int G = out_size;
    int NB = (N + 1023) / 1024;

    // CSR by destination node
    k_zero_cnt<<<(N + 255) / 256, 256>>>(N);
    k_hist<<<(E + 255) / 256, 256>>>(ei, E);
    k_scan1<<<NB, 1024>>>(N);
    k_scan2<<<1, 64>>>(NB);
    k_scan3<<<NB, 1024>>>(N, E);
    k_scatter<<<(E + 255) / 256, 256>>>(ei, E);

    // embedding: h = relu(x @ W_emb + b_emb)
    k_gemm_tc<FN, 0><<<(N + 127) / 128, 256>>>(x, W_emb, b_emb, nullptr, nullptr, N);

    // layer-invariant edge-attr aggregation into X[:,128:192]
    k_se<<<(N * 32 + 255) / 256, 256>>>(ea, N);

    for (int l = 0; l < NLAYER; l++) {
        k_spmm<<<(N * 32 + 255) / 256, 256>>>(N);
        k_gemm_tc<KX, 1><<<(N + 127) / 128, 256>>>(nullptr, Wc + (size_t)l * KX * HDIM,
                                                   bc + l * HDIM, gamma + l * HDIM,
                                                   beta + l * HDIM, N);
    }

    k_head<<<G, 128>>>(batch, Wh, bh, Wout, bout, out, N);
}

// round 7
// speedup vs baseline: 1.5991x; 1.0412x over previous
#include <cuda_runtime.h>
#include <cuda_fp16.h>
#include <cstdint>

#define MAXN 50000
#define MAXE 800000
#define HDIM 128
#define FE 64
#define FN 92
#define KX 192          // HDIM + FE
#define NLAYER 3
#define BN_EPS 1e-3f

// ---------------- scratch (static device globals; no allocation) ----------------
__device__ float  d_h[MAXN * HDIM];        // node features (fp32, for residual+pool)
__device__ __half d_hh[MAXN * HDIM];       // fp16 mirror of h (SpMM gather source)
__device__ float  d_X[MAXN * KX];          // [ sum h[col] | sum edge_attr ] per node
__device__ int    d_cnt[MAXN];             // in-degree counts
__device__ int    d_off[MAXN + 1];         // CSR offsets by destination (row)
__device__ int    d_cur[MAXN];             // scatter cursors
__device__ int    d_cols[MAXE];            // source node (col) sorted by destination
__device__ int    d_eid[MAXE];             // original edge id sorted by destination
__device__ int    d_bsum[64];              // per-block scan totals
__device__ int    d_bbase[64];             // per-block scan bases

struct __align__(8) H4 { __half2 a, b; };

// ---------------- CSR build ----------------
__global__ void k_zero_cnt(int n) {
    int i = blockIdx.x * blockDim.x + threadIdx.x;
    if (i < n) d_cnt[i] = 0;
}

__global__ void k_hist(const int* __restrict__ ei, int E) {
    int e = blockIdx.x * blockDim.x + threadIdx.x;
    if (e < E) atomicAdd(&d_cnt[ei[e]], 1);
}

// block-local exclusive scan of d_cnt into d_off (temp), block totals to d_bsum
__global__ void k_scan1(int N) {
    __shared__ int s[32];
    int t = threadIdx.x;
    int i = blockIdx.x * 1024 + t;
    int lane = t & 31, w = t >> 5;
    int c = (i < N) ? d_cnt[i] : 0;
    int v = c;
#pragma unroll
    for (int d = 1; d < 32; d <<= 1) {
        int u = __shfl_up_sync(0xffffffffu, v, d);
        if (lane >= d) v += u;
    }
    if (lane == 31) s[w] = v;
    __syncthreads();
    if (w == 0) {
        int sv = s[lane];
#pragma unroll
        for (int d = 1; d < 32; d <<= 1) {
            int u = __shfl_up_sync(0xffffffffu, sv, d);
            if (lane >= d) sv += u;
        }
        s[lane] = sv;
    }
    __syncthreads();
    int base = (w > 0) ? s[w - 1] : 0;
    int incl = v + base;
    if (i < N) d_off[i] = incl - c;        // block-local exclusive
    if (t == 1023) d_bsum[blockIdx.x] = incl;
}

// exclusive scan of block totals (NB <= 64), 1 block of 64 threads
__global__ void k_scan2(int NB) {
    __shared__ int s[2];
    int t = threadIdx.x;
    int lane = t & 31, w = t >> 5;
    int c = (t < NB) ? d_bsum[t] : 0;
    int v = c;
#pragma unroll
    for (int d = 1; d < 32; d <<= 1) {
        int u = __shfl_up_sync(0xffffffffu, v, d);
        if (lane >= d) v += u;
    }
    if (lane == 31) s[w] = v;
    __syncthreads();
    int base = (w > 0) ? s[0] : 0;
    if (t < NB) d_bbase[t] = v + base - c;  // exclusive
}

__global__ void k_scan3(int N, int E) {
    int i = blockIdx.x * blockDim.x + threadIdx.x;
    if (i < N) {
        int v = d_off[i] + d_bbase[i >> 10];
        d_off[i] = v;
        d_cur[i] = v;
    }
    if (i == 0) d_off[N] = E;
}

__global__ void k_scatter(const int* __restrict__ ei, int E) {
    int e = blockIdx.x * blockDim.x + threadIdx.x;
    if (e < E) {
        int r = ei[e];
        int c = ei[E + e];
        int p = atomicAdd(&d_cur[r], 1);
        d_cols[p] = c;
        d_eid[p]  = e;
    }
}

// ---------------- SpMM: X[:,0:128] = sum_{in-edges} h_fp16[col]
// FIRST==1 additionally computes X[:,128:192] = sum_{in-edges} edge_attr[eid]
// (DRAM-bound ea stream overlaps the L2-bound h gather in the same loop)
template <int FIRST>
__launch_bounds__(256)
__global__ void k_spmm(const float* __restrict__ ea, int N) {
    int gw   = (blockIdx.x * blockDim.x + threadIdx.x) >> 5;
    int lane = threadIdx.x & 31;
    if (gw >= N) return;
    int lo = d_off[gw], hi = d_off[gw + 1];
    float4 acc = make_float4(0.f, 0.f, 0.f, 0.f);
    float2 eacc = make_float2(0.f, 0.f);
    int j = lo;
    for (; j + 4 <= hi; j += 4) {
        int c0 = d_cols[j],     c1 = d_cols[j + 1];
        int c2 = d_cols[j + 2], c3 = d_cols[j + 3];
        H4 v0 = *(const H4*)(d_hh + (size_t)c0 * HDIM + lane * 4);
        H4 v1 = *(const H4*)(d_hh + (size_t)c1 * HDIM + lane * 4);
        H4 v2 = *(const H4*)(d_hh + (size_t)c2 * HDIM + lane * 4);
        H4 v3 = *(const H4*)(d_hh + (size_t)c3 * HDIM + lane * 4);
        if (FIRST) {
            int e0 = d_eid[j],     e1 = d_eid[j + 1];
            int e2 = d_eid[j + 2], e3 = d_eid[j + 3];
            float2 w0 = *(const float2*)(ea + (size_t)e0 * FE + lane * 2);
            float2 w1 = *(const float2*)(ea + (size_t)e1 * FE + lane * 2);
            float2 w2 = *(const float2*)(ea + (size_t)e2 * FE + lane * 2);
            float2 w3 = *(const float2*)(ea + (size_t)e3 * FE + lane * 2);
            eacc.x += (w0.x + w1.x) + (w2.x + w3.x);
            eacc.y += (w0.y + w1.y) + (w2.y + w3.y);
        }
        float2 a0 = __half22float2(v0.a), b0 = __half22float2(v0.b);
        float2 a1 = __half22float2(v1.a), b1 = __half22float2(v1.b);
        float2 a2 = __half22float2(v2.a), b2 = __half22float2(v2.b);
        float2 a3 = __half22float2(v3.a), b3 = __half22float2(v3.b);
        acc.x += (a0.x + a1.x) + (a2.x + a3.x);
        acc.y += (a0.y + a1.y) + (a2.y + a3.y);
        acc.z += (b0.x + b1.x) + (b2.x + b3.x);
        acc.w += (b0.y + b1.y) + (b2.y + b3.y);
    }
    for (; j < hi; j++) {
        int c0 = d_cols[j];
        H4 v0 = *(const H4*)(d_hh + (size_t)c0 * HDIM + lane * 4);
        if (FIRST) {
            int e0 = d_eid[j];
            float2 w0 = *(const float2*)(ea + (size_t)e0 * FE + lane * 2);
            eacc.x += w0.x; eacc.y += w0.y;
        }
        float2 a0 = __half22float2(v0.a), b0 = __half22float2(v0.b);
        acc.x += a0.x; acc.y += a0.y; acc.z += b0.x; acc.w += b0.y;
    }
    *(float4*)(d_X + (size_t)gw * KX + lane * 4) = acc;
    if (FIRST)
        *(float2*)(d_X + (size_t)gw * KX + HDIM + lane * 2) = eacc;
}

// ---------------- tf32 tensor-core GEMM: C[N,128] = A[N,K] @ W[K,128] + epilogue ----------------
__device__ __forceinline__ uint32_t f2tf32(float f) {
    uint32_t r;
    asm("cvt.rna.tf32.f32 %0, %1;" : "=r"(r) : "f"(f));
    return r;
}

template <int K, int EPI>
__launch_bounds__(256)
__global__ void k_gemm_tc(const float* __restrict__ Ain,
                          const float* __restrict__ W,
                          const float* __restrict__ bias,
                          const float* __restrict__ gamma,
                          const float* __restrict__ beta,
                          int N) {
    constexpr int KC = 32;
    constexpr int KTILES = (K + KC - 1) / KC;
    constexpr int AS_STRIDE = 36;   // 128 x 32, padded
    constexpr int BS_STRIDE = 132;  // 32 x 128, padded
    __shared__ __align__(16) float As[128 * AS_STRIDE];
    __shared__ __align__(16) float Bs[32 * BS_STRIDE];

    const float* A = (EPI == 1) ? (const float*)d_X : Ain;

    const int tid  = threadIdx.x;
    const int wid  = tid >> 5;
    const int lane = tid & 31;
    const int warp_m = wid & 3;   // 0..3 -> 32-row slabs
    const int warp_n = wid >> 2;  // 0..1 -> 64-col slabs
    const int gID = lane >> 2;    // group id 0..7
    const int tig = lane & 3;     // thread-in-group 0..3
    const int rowBase = blockIdx.x * 128;

    float acc[2][8][4];
#pragma unroll
    for (int mf = 0; mf < 2; mf++)
#pragma unroll
        for (int nf = 0; nf < 8; nf++)
#pragma unroll
            for (int c = 0; c < 4; c++) acc[mf][nf][c] = 0.f;

    for (int kt = 0; kt < KTILES; kt++) {
        const int k0 = kt * KC;
        // stage A: 128 rows x 32 k
        {
            int r = tid >> 3;          // 0..31
            int k4 = (tid & 7) * 4;    // 0,4,..,28
#pragma unroll
            for (int it = 0; it < 4; it++) {
                int row = r + it * 32;
                int grow = rowBase + row;
                int kg = k0 + k4;
                float4 v = make_float4(0.f, 0.f, 0.f, 0.f);
                if (grow < N && kg + 4 <= K)
                    v = *(const float4*)(A + (size_t)grow * K + kg);
                *(float4*)&As[row * AS_STRIDE + k4] = v;
            }
        }
        // stage B: 32 k x 128 n
        {
            int kk = tid >> 5;         // 0..7
            int c4 = (tid & 31) * 4;   // 0..124
#pragma unroll
            for (int it = 0; it < 4; it++) {
                int krow = kk + it * 8;
                int kg = k0 + krow;
                float4 v = make_float4(0.f, 0.f, 0.f, 0.f);
                if (kg < K)
                    v = *(const float4*)(W + (size_t)kg * HDIM + c4);
                *(float4*)&Bs[krow * BS_STRIDE + c4] = v;
            }
        }
        __syncthreads();

#pragma unroll
        for (int k8 = 0; k8 < KC / 8; k8++) {
            const int kb = k8 * 8;
            uint32_t bfr[8][2];
#pragma unroll
            for (int nf = 0; nf < 8; nf++) {
                int col = warp_n * 64 + nf * 8 + gID;
                bfr[nf][0] = f2tf32(Bs[(kb + tig) * BS_STRIDE + col]);
                bfr[nf][1] = f2tf32(Bs[(kb + tig + 4) * BS_STRIDE + col]);
            }
#pragma unroll
            for (int mf = 0; mf < 2; mf++) {
                int r0 = warp_m * 32 + mf * 16 + gID;
                uint32_t a0 = f2tf32(As[r0 * AS_STRIDE + kb + tig]);
                uint32_t a1 = f2tf32(As[(r0 + 8) * AS_STRIDE + kb + tig]);
                uint32_t a2 = f2tf32(As[r0 * AS_STRIDE + kb + tig + 4]);
                uint32_t a3 = f2tf32(As[(r0 + 8) * AS_STRIDE + kb + tig + 4]);
#pragma unroll
                for (int nf = 0; nf < 8; nf++) {
                    asm volatile(
                        "mma.sync.aligned.m16n8k8.row.col.f32.tf32.tf32.f32 "
                        "{%0,%1,%2,%3}, {%4,%5,%6,%7}, {%8,%9}, {%0,%1,%2,%3};\n"
                        : "+f"(acc[mf][nf][0]), "+f"(acc[mf][nf][1]),
                          "+f"(acc[mf][nf][2]), "+f"(acc[mf][nf][3])
                        : "r"(a0), "r"(a1), "r"(a2), "r"(a3),
                          "r"(bfr[nf][0]), "r"(bfr[nf][1]));
                }
            }
        }
        __syncthreads();
    }

    // epilogue: write fp32 d_h and fp16 mirror d_hh
    const float sc = rsqrtf(1.f + BN_EPS);
#pragma unroll
    for (int mf = 0; mf < 2; mf++) {
        int r0 = rowBase + warp_m * 32 + mf * 16 + gID;
        int r1 = r0 + 8;
        float inv0 = 1.f, inv1 = 1.f;
        if (EPI == 1) {
            if (r0 < N) inv0 = 1.f / (float)max(d_cnt[r0], 1);
            if (r1 < N) inv1 = 1.f / (float)max(d_cnt[r1], 1);
        }
#pragma unroll
        for (int nf = 0; nf < 8; nf++) {
            int c0 = warp_n * 64 + nf * 8 + 2 * tig;
#pragma unroll
            for (int cc = 0; cc < 2; cc++) {
                int c = c0 + cc;
                float b = bias[c];
                if (EPI == 0) {
                    if (r0 < N) {
                        float v = fmaxf(acc[mf][nf][cc] + b, 0.f);
                        d_h[(size_t)r0 * HDIM + c] = v;
                        d_hh[(size_t)r0 * HDIM + c] = __float2half_rn(v);
                    }
                    if (r1 < N) {
                        float v = fmaxf(acc[mf][nf][2 + cc] + b, 0.f);
                        d_h[(size_t)r1 * HDIM + c] = v;
                        d_hh[(size_t)r1 * HDIM + c] = __float2half_rn(v);
                    }
                } else {
                    float g = gamma[c] * sc;
                    float be = beta[c];
                    if (r0 < N) {
                        float v = acc[mf][nf][cc] * inv0 + b;
                        v = v * g + be;
                        float nh = d_h[(size_t)r0 * HDIM + c] + fmaxf(v, 0.f);
                        d_h[(size_t)r0 * HDIM + c] = nh;
                        d_hh[(size_t)r0 * HDIM + c] = __float2half_rn(nh);
                    }
                    if (r1 < N) {
                        float v = acc[mf][nf][2 + cc] * inv1 + b;
                        v = v * g + be;
                        float nh = d_h[(size_t)r1 * HDIM + c] + fmaxf(v, 0.f);
                        d_h[(size_t)r1 * HDIM + c] = nh;
                        d_hh[(size_t)r1 * HDIM + c] = __float2half_rn(nh);
                    }
                }
            }
        }
    }
}

// ---------------- fused mean-pool + hidden + head (batch_idx sorted) ----------------
__launch_bounds__(128)
__global__ void k_head(const int* __restrict__ batch,
                       const float* __restrict__ Wh,
                       const float* __restrict__ bh,
                       const float* __restrict__ Wout,
                       const float* __restrict__ bout,
                       float* __restrict__ out, int N) {
    int b = blockIdx.x;
    int t = threadIdx.x;
    __shared__ float gv[HDIM];
    __shared__ float red[HDIM];
    __shared__ int srange[2];
    if (t < 2) {
        int v = b + t;
        int lo = 0, hi = N;
        while (lo < hi) {
            int m = (lo + hi) >> 1;
            if (batch[m] < v) lo = m + 1; else hi = m;
        }
        srange[t] = lo;
    }
    __syncthreads();
    int lo = srange[0], hi = srange[1];
    float s = 0.f;
    for (int r = lo; r < hi; r++) s += d_h[(size_t)r * HDIM + t];
    gv[t] = s / (float)max(hi - lo, 1);
    __syncthreads();
    float hd = bh[t];
#pragma unroll 8
    for (int k = 0; k < HDIM; k++) hd = fmaf(gv[k], Wh[k * HDIM + t], hd);
    hd = fmaxf(hd, 0.f);
    red[t] = hd * Wout[t];
    __syncthreads();
    for (int s2 = 64; s2 > 0; s2 >>= 1) {
        if (t < s2) red[t] += red[t + s2];
        __syncthreads();
    }
    if (t == 0) out[b] = red[0] + bout[0];
}

// ---------------- launch ----------------
extern "C" void kernel_launch(void* const* d_in, const int* in_sizes, int n_in,
                              void* d_out, int out_size) {
    const float* x     = (const float*)d_in[0];
    const int*   ei    = (const int*)  d_in[1];
    const float* ea    = (const float*)d_in[2];
    const int*   batch = (const int*)  d_in[3];
    const float* W_emb = (const float*)d_in[4];
    const float* b_emb = (const float*)d_in[5];
    const float* Wc    = (const float*)d_in[6];
    const float* bc    = (const float*)d_in[7];
    const float* gamma = (const float*)d_in[8];
    const float* beta  = (const float*)d_in[9];
    const float* Wh    = (const float*)d_in[10];
    const float* bh    = (const float*)d_in[11];
    const float* Wout  = (const float*)d_in[12];
    const float* bout  = (const float*)d_in[13];
    float* out = (float*)d_out;

    int N = in_sizes[0] / FN;
    int E = in_sizes[1] / 2;
    int G = out_size;
    int NB = (N + 1023) / 1024;

    // CSR by destination node (launches 0..4)
    k_zero_cnt<<<(N + 255) / 256, 256>>>(N);
    k_hist<<<(E + 255) / 256, 256>>>(ei, E);
    k_scan1<<<NB, 1024>>>(N);
    k_scan2<<<1, 64>>>(NB);
    k_scan3<<<NB, 1024>>>(N, E);

    // embedding: h = relu(x @ W_emb + b_emb)   (launch 5 -> ncu profiles this)
    k_gemm_tc<FN, 0><<<(N + 127) / 128, 256>>>(x, W_emb, b_emb, nullptr, nullptr, N);

    k_scatter<<<(E + 255) / 256, 256>>>(ei, E);

    // layer 0: fused h-gather + edge-attr aggregation
    k_spmm<1><<<(N * 32 + 255) / 256, 256>>>(ea, N);
    k_gemm_tc<KX, 1><<<(N + 127) / 128, 256>>>(nullptr, Wc, bc, gamma, beta, N);

    for (int l = 1; l < NLAYER; l++) {
        k_spmm<0><<<(N * 32 + 255) / 256, 256>>>(ea, N);
        k_gemm_tc<KX, 1><<<(N + 127) / 128, 256>>>(nullptr, Wc + (size_t)l * KX * HDIM,
                                                   bc + l * HDIM, gamma + l * HDIM,
                                                   beta + l * HDIM, N);
    }

    k_head<<<G, 128>>>(batch, Wh, bh, Wout, bout, out, N);
}